// round 1
// baseline (speedup 1.0000x reference)
#include <cuda_runtime.h>
#include <math.h>

#define BMAX 16
#define TMAX 64

__constant__ float c_anchx[9] = {10.f,16.f,33.f,30.f,62.f,59.f,116.f,156.f,373.f};
__constant__ float c_anchy[9] = {13.f,30.f,23.f,61.f,45.f,119.f,90.f,198.f,326.f};

// scratch (no allocations allowed)
__device__ float4 g_box[BMAX*TMAX];    // target box tl.x,tl.y,br.x,br.y (grid units)
__device__ float2 g_meta[BMAX*TMAX];   // (0.7*area_b, key-as-float-bits)
__device__ float  g_ext[BMAX*TMAX*8];  // fx,fy,logw,logh,scale,cls
__device__ int    g_cnt[BMAX];
__device__ double g_acc;

__global__ void k_init() { g_acc = 0.0; }
__global__ void k_fin(float* out) { out[0] = (float)g_acc; }

__device__ __forceinline__ float slog(float x) { return x > 0.f ? __logf(x) : -100.f; }
__device__ __forceinline__ float sigm(float x) { return 1.f/(1.f + __expf(-x)); }

// Per-layer target preprocessing: one thread per batch, serial over T targets,
// compacting valid ones in order (preserves last-wins scatter ordering).
__global__ void k_tgt(const float* __restrict__ tg, int B, int T, int fs,
                      int group, float stride)
{
    int b = blockIdx.x*blockDim.x + threadIdx.x;
    if (b >= B) return;
    float fsf = (float)fs;
    int cnt = 0;
    for (int t = 0; t < T; ++t) {
        const float* L = tg + ((size_t)b*T + t)*5;
        float cf = L[0], x = L[1], y = L[2], w = L[3], h = L[4];
        if (!((cf + x + y + w + h) > 0.f)) continue;   // valid = sum(labels) > 0
        float tx = x*fsf, ty = y*fsf, tw = w*fsf, th = h*fsf;
        float twth = tw*th;
        // argmax over 9 anchor IoUs (first max wins, matching jnp.argmax)
        float best = -1.f; int bi = 0;
        #pragma unroll
        for (int i = 0; i < 9; ++i) {
            float aw = c_anchx[i]/stride, ah = c_anchy[i]/stride;
            float mw = fminf(tw, aw), mh = fminf(th, ah);
            float inter = (mw > 0.f && mh > 0.f) ? mw*mh : 0.f;
            float iou = inter / (twth + aw*ah - inter);
            if (iou > best) { best = iou; bi = i; }
        }
        int bn = bi - (bi/3)*3;
        bool sel = (bi/3) == group;
        int idx = b*TMAX + cnt;
        g_box[idx] = make_float4(tx - 0.5f*tw, ty - 0.5f*th, tx + 0.5f*tw, ty + 0.5f*th);
        int key = -1;
        if (sel) {
            int gi = (int)tx, gj = (int)ty;
            if (gi >= 0 && gi < fs && gj >= 0 && gj < fs) {   // mode='drop'
                key = (bn << 28) | (gj << 14) | gi;
                float aw = c_anchx[group*3 + bn]/stride;
                float ah = c_anchy[group*3 + bn]/stride;
                float* e = g_ext + (size_t)idx*8;
                e[0] = tx - (float)gi;
                e[1] = ty - (float)gj;
                e[2] = logf(tw/aw + 1e-16f);
                e[3] = logf(th/ah + 1e-16f);
                e[4] = sqrtf(2.f - twth/(fsf*fsf));
                e[5] = __int_as_float((int)cf);
            }
        }
        g_meta[idx] = make_float2(0.7f*twth, __int_as_float(key));
        cnt++;
    }
    g_cnt[b] = cnt;
}

// Main per-cell loss kernel: grid.y = batch, grid.x covers A*H*W cells.
__global__ __launch_bounds__(256)
void k_loss(const float* __restrict__ raw, int HW, int W,
            float m0x, float m0y, float m1x, float m1y, float m2x, float m2y)
{
    __shared__ float4 sbox[TMAX];
    __shared__ float2 smeta[TMAX];
    __shared__ int scnt;

    int b = blockIdx.y;
    int tid = threadIdx.x;
    if (tid == 0) scnt = g_cnt[b];
    if (tid < TMAX) {
        int gidx = b*TMAX + tid;
        sbox[tid]  = g_box[gidx];
        smeta[tid] = g_meta[gidx];
    }
    __syncthreads();

    int cell = blockIdx.x*blockDim.x + tid;
    float lsum = 0.f;
    if (cell < 3*HW) {
        int a  = cell / HW;
        int hw = cell - a*HW;
        int h  = hw / W;
        int w  = hw - h*W;
        const float* p = raw + ((size_t)b*255 + (size_t)a*85)*(size_t)HW + hw;
        float o0 = __ldg(p);
        float o1 = __ldg(p + HW);
        float o2 = __ldg(p + 2*HW);
        float o3 = __ldg(p + 3*HW);
        float o4 = __ldg(p + 4*HW);
        float s0 = sigm(o0), s1 = sigm(o1), s4 = sigm(o4);
        float maw = (a == 0) ? m0x : ((a == 1) ? m1x : m2x);
        float mah = (a == 0) ? m0y : ((a == 1) ? m1y : m2y);
        float pw = __expf(o2)*maw, ph = __expf(o3)*mah;
        float px = s0 + (float)w, py = s1 + (float)h;
        float atlx = px - 0.5f*pw, atly = py - 0.5f*ph;
        float abrx = px + 0.5f*pw, abry = py + 0.5f*ph;
        float ca = 0.7f*(pw*ph);
        int ckey = (a << 28) | (h << 14) | w;

        bool any = false;
        int tmi = -1;
        int cnt = scnt;
        for (int t = 0; t < cnt; ++t) {
            float4 bb = sbox[t];
            float2 mm = smeta[t];
            float ix = fminf(abrx, bb.z) - fmaxf(atlx, bb.x);
            float iy = fminf(abry, bb.w) - fmaxf(atly, bb.y);
            float ai = ix*iy;
            // piou > 0.7  <=>  ix>0 & iy>0 & 1.7*ai > 0.7*(area_a+area_b)
            if (ix > 0.f && iy > 0.f && 1.7f*ai > ca + mm.x) any = true;
            if (__float_as_int(mm.y) == ckey) tmi = t;   // last match wins
        }

        if (tmi >= 0) {
            const float* e = g_ext + ((size_t)b*TMAX + tmi)*8;
            float fx = e[0], fy = e[1], tlw = e[2], tlh = e[3], sc = e[4];
            int cls = __float_as_int(e[5]);
            float ts2 = sc*sc;
            // BCE(xy) weighted by scale^2
            lsum -= ts2*( fx*slog(s0) + (1.f - fx)*slog(1.f - s0)
                        + fy*slog(s1) + (1.f - fy)*slog(1.f - s1) );
            // 0.5 * scale^2 * (wh diff)^2
            float dw = o2 - tlw, dh = o3 - tlh;
            lsum += 0.5f*ts2*(dw*dw + dh*dh);
            // obj BCE with target 1 (obj_mask forced to 1 here)
            lsum -= slog(s4);
            // class BCE over 80 channels (only at assigned cells)
            for (int c = 0; c < 80; ++c) {
                float oc = __ldg(p + (size_t)(5 + c)*HW);
                float scc = sigm(oc);
                lsum -= (c == cls) ? slog(scc) : slog(1.f - scc);
            }
        } else if (!any) {
            // obj BCE with target 0 where obj_mask = 1
            lsum -= slog(1.f - s4);
        }
        // (any && tmi<0) -> obj_mask = 0 -> zero contribution
    }

    // warp reduction + double accumulation
    #pragma unroll
    for (int off = 16; off; off >>= 1)
        lsum += __shfl_xor_sync(0xffffffffu, lsum, off);
    if ((tid & 31) == 0)
        atomicAdd(&g_acc, (double)lsum);
}

extern "C" void kernel_launch(void* const* d_in, const int* in_sizes, int n_in,
                              void* d_out, int out_size)
{
    const float* outs[3] = {(const float*)d_in[0], (const float*)d_in[1], (const float*)d_in[2]};
    const float* targets = (const float*)d_in[3];
    const int B = 16;
    int T = in_sizes[3] / (B*5);
    if (T > TMAX) T = TMAX;

    static const float AX[9] = {10.f,16.f,33.f,30.f,62.f,59.f,116.f,156.f,373.f};
    static const float AY[9] = {13.f,30.f,23.f,61.f,45.f,119.f,90.f,198.f,326.f};
    const float strides[3] = {32.f, 16.f, 8.f};
    const int   groups[3]  = {2, 1, 0};

    k_init<<<1,1>>>();
    for (int l = 0; l < 3; ++l) {
        int HW = in_sizes[l] / (B*255);
        int Wd = (int)(sqrt((double)HW) + 0.5);
        k_tgt<<<1, B>>>(targets, B, T, Wd, groups[l], strides[l]);
        float m[6];
        for (int i = 0; i < 3; ++i) {
            m[2*i]   = AX[groups[l]*3 + i] / strides[l];
            m[2*i+1] = AY[groups[l]*3 + i] / strides[l];
        }
        dim3 grid((3*HW + 255)/256, B);
        k_loss<<<grid, 256>>>(outs[l], HW, Wd, m[0], m[1], m[2], m[3], m[4], m[5]);
    }
    k_fin<<<1,1>>>((float*)d_out);
}

// round 2
// speedup vs baseline: 4.3290x; 4.3290x over previous
#include <cuda_runtime.h>
#include <math.h>

#define BMAX 16
#define TMAX 64

__constant__ float c_anchx[9] = {10.f,16.f,33.f,30.f,62.f,59.f,116.f,156.f,373.f};
__constant__ float c_anchy[9] = {13.f,30.f,23.f,61.f,45.f,119.f,90.f,198.f,326.f};
// manch per layer (= ANCHORS[group*3+a]/stride), layer order group={2,1,0}, stride={32,16,8}
__constant__ float c_manch[3][6] = {
    {3.625f, 2.8125f, 4.875f, 6.1875f, 11.65625f, 10.1875f},
    {1.875f, 3.8125f, 3.875f, 2.8125f, 3.6875f,   7.4375f},
    {1.25f,  1.625f,  2.0f,   3.75f,   4.125f,    2.875f }
};
__constant__ float c_stride[3] = {32.f, 16.f, 8.f};

// scratch (no allocations allowed)
__device__ float4 g_box[3*BMAX*TMAX];    // target box tl.x,tl.y,br.x,br.y (grid units)
__device__ float2 g_meta[3*BMAX*TMAX];   // (0.7*area_b, key-as-float-bits)
__device__ float  g_ext[3*BMAX*TMAX*8];  // fx,fy,logw,logh,scale,cls
__device__ int    g_cnt[3*BMAX];
__device__ double g_acc;

__global__ void k_fin(float* out) { out[0] = (float)g_acc; }

__device__ __forceinline__ float slog(float x) { return x > 0.f ? __logf(x) : -100.f; }
__device__ __forceinline__ float sigm(float x) { return 1.f/(1.f + __expf(-x)); }

// Fused target preprocessing for all 3 layers: grid (B, 3), 64 threads.
// One thread per target; ballot prefix-sum compacts valid targets preserving order.
__global__ void k_tgt(const float* __restrict__ tg, int T,
                      int fs0, int fs1, int fs2)
{
    int b     = blockIdx.x;
    int layer = blockIdx.y;
    int tid   = threadIdx.x;          // 0..63
    if (b == 0 && layer == 0 && tid == 0) g_acc = 0.0;

    int fs = (layer == 0) ? fs0 : ((layer == 1) ? fs1 : fs2);
    float stride = c_stride[layer];
    int group = 2 - layer;
    float fsf = (float)fs;

    bool valid = false;
    float cf = 0.f, tx = 0.f, ty = 0.f, tw = 0.f, th = 0.f;
    if (tid < T) {
        const float* L = tg + ((size_t)b*T + tid)*5;
        cf = L[0];
        float x = L[1], y = L[2], w = L[3], h = L[4];
        valid = (cf + x + y + w + h) > 0.f;
        tx = x*fsf; ty = y*fsf; tw = w*fsf; th = h*fsf;
    }

    // order-preserving compaction index
    __shared__ int s_w0;
    int lane = tid & 31, wi = tid >> 5;
    unsigned ball = __ballot_sync(0xffffffffu, valid);
    int pre = __popc(ball & ((1u << lane) - 1u));
    if (wi == 0 && lane == 0) s_w0 = __popc(ball);
    __syncthreads();
    if (wi == 1) pre += s_w0;
    if (tid == 63) g_cnt[layer*BMAX + b] = s_w0 + __popc(ball);

    if (!valid) return;

    float twth = tw*th;
    // argmax over 9 anchor IoUs (first max wins, matching jnp.argmax)
    float best = -1.f; int bi = 0;
    #pragma unroll
    for (int i = 0; i < 9; ++i) {
        float aw = c_anchx[i]/stride, ah = c_anchy[i]/stride;
        float mw = fminf(tw, aw), mh = fminf(th, ah);
        float inter = (mw > 0.f && mh > 0.f) ? mw*mh : 0.f;
        float iou = inter / (twth + aw*ah - inter);
        if (iou > best) { best = iou; bi = i; }
    }
    int bn = bi - (bi/3)*3;
    bool sel = (bi/3) == group;

    int idx = (layer*BMAX + b)*TMAX + pre;
    g_box[idx] = make_float4(tx - 0.5f*tw, ty - 0.5f*th, tx + 0.5f*tw, ty + 0.5f*th);
    int key = -1;
    if (sel) {
        int gi = (int)tx, gj = (int)ty;
        if (gi >= 0 && gi < fs && gj >= 0 && gj < fs) {   // mode='drop'
            key = (bn << 28) | (gj << 14) | gi;
            float aw = c_manch[layer][2*bn];
            float ah = c_manch[layer][2*bn + 1];
            float* e = g_ext + (size_t)idx*8;
            e[0] = tx - (float)gi;
            e[1] = ty - (float)gj;
            e[2] = logf(tw/aw + 1e-16f);
            e[3] = logf(th/ah + 1e-16f);
            e[4] = sqrtf(2.f - twth/(fsf*fsf));
            e[5] = __int_as_float((int)cf);
        }
    }
    g_meta[idx] = make_float2(0.7f*twth, __int_as_float(key));
}

// Fused per-cell loss for all 3 layers.
// blockIdx.x partitions: [0,nb0)=layer0, [nb0,nb01)=layer1, rest=layer2. blockIdx.y = batch.
__global__ __launch_bounds__(256)
void k_loss(const float* __restrict__ r0, const float* __restrict__ r1,
            const float* __restrict__ r2,
            int HW0, int W0, int HW1, int W1, int HW2, int W2,
            int nb0, int nb01)
{
    __shared__ float4 sbox[TMAX];
    __shared__ float2 smeta[TMAX];
    __shared__ int scnt;

    int bx = blockIdx.x;
    int layer; const float* raw; int HW, W, base;
    if (bx < nb0)       { layer = 0; raw = r0; HW = HW0; W = W0; base = 0;    }
    else if (bx < nb01) { layer = 1; raw = r1; HW = HW1; W = W1; base = nb0;  }
    else                { layer = 2; raw = r2; HW = HW2; W = W2; base = nb01; }

    int b = blockIdx.y;
    int tid = threadIdx.x;
    int lb = layer*BMAX + b;
    if (tid == 0) scnt = g_cnt[lb];
    if (tid < TMAX) {
        int gidx = lb*TMAX + tid;
        sbox[tid]  = g_box[gidx];
        smeta[tid] = g_meta[gidx];
    }
    __syncthreads();

    int cell = (bx - base)*256 + tid;
    float lsum = 0.f;
    if (cell < 3*HW) {
        int a  = cell / HW;
        int hw = cell - a*HW;
        int h  = hw / W;
        int w  = hw - h*W;
        const float* p = raw + ((size_t)b*255 + (size_t)a*85)*(size_t)HW + hw;
        float o0 = __ldg(p);
        float o1 = __ldg(p + HW);
        float o2 = __ldg(p + 2*HW);
        float o3 = __ldg(p + 3*HW);
        float o4 = __ldg(p + 4*HW);
        float s0 = sigm(o0), s1 = sigm(o1), s4 = sigm(o4);
        float maw = c_manch[layer][2*a];
        float mah = c_manch[layer][2*a + 1];
        float pw = __expf(o2)*maw, ph = __expf(o3)*mah;
        float px = s0 + (float)w, py = s1 + (float)h;
        float atlx = px - 0.5f*pw, atly = py - 0.5f*ph;
        float abrx = px + 0.5f*pw, abry = py + 0.5f*ph;
        float ca = 0.7f*(pw*ph);
        int ckey = (a << 28) | (h << 14) | w;

        bool any = false;
        int tmi = -1;
        int cnt = scnt;
        for (int t = 0; t < cnt; ++t) {
            float4 bb = sbox[t];
            float2 mm = smeta[t];
            float ix = fminf(abrx, bb.z) - fmaxf(atlx, bb.x);
            float iy = fminf(abry, bb.w) - fmaxf(atly, bb.y);
            float ai = ix*iy;
            // piou > 0.7  <=>  ix>0 & iy>0 & 1.7*ai > 0.7*(area_a+area_b)
            if (ix > 0.f && iy > 0.f && 1.7f*ai > ca + mm.x) any = true;
            if (__float_as_int(mm.y) == ckey) tmi = t;   // last match wins
        }

        if (tmi >= 0) {
            const float* e = g_ext + ((size_t)lb*TMAX + tmi)*8;
            float fx = e[0], fy = e[1], tlw = e[2], tlh = e[3], sc = e[4];
            int cls = __float_as_int(e[5]);
            float ts2 = sc*sc;
            // BCE(xy) weighted by scale^2
            lsum -= ts2*( fx*slog(s0) + (1.f - fx)*slog(1.f - s0)
                        + fy*slog(s1) + (1.f - fy)*slog(1.f - s1) );
            // 0.5 * scale^2 * (wh diff)^2
            float dw = o2 - tlw, dh = o3 - tlh;
            lsum += 0.5f*ts2*(dw*dw + dh*dh);
            // obj BCE with target 1
            lsum -= slog(s4);
            // class BCE over 80 channels (only at assigned cells)
            for (int c = 0; c < 80; ++c) {
                float oc = __ldg(p + (size_t)(5 + c)*HW);
                float scc = sigm(oc);
                lsum -= (c == cls) ? slog(scc) : slog(1.f - scc);
            }
        } else if (!any) {
            // obj BCE with target 0 where obj_mask = 1
            lsum -= slog(1.f - s4);
        }
        // (any && tmi<0) -> obj_mask = 0 -> zero contribution
    }

    // warp reduction + double accumulation
    #pragma unroll
    for (int off = 16; off; off >>= 1)
        lsum += __shfl_xor_sync(0xffffffffu, lsum, off);
    if ((tid & 31) == 0)
        atomicAdd(&g_acc, (double)lsum);
}

extern "C" void kernel_launch(void* const* d_in, const int* in_sizes, int n_in,
                              void* d_out, int out_size)
{
    const float* r0 = (const float*)d_in[0];
    const float* r1 = (const float*)d_in[1];
    const float* r2 = (const float*)d_in[2];
    const float* targets = (const float*)d_in[3];
    const int B = 16;
    int T = in_sizes[3] / (B*5);
    if (T > TMAX) T = TMAX;

    int HW0 = in_sizes[0] / (B*255);
    int HW1 = in_sizes[1] / (B*255);
    int HW2 = in_sizes[2] / (B*255);
    int W0 = (int)(sqrt((double)HW0) + 0.5);
    int W1 = (int)(sqrt((double)HW1) + 0.5);
    int W2 = (int)(sqrt((double)HW2) + 0.5);

    dim3 tgrid(B, 3);
    k_tgt<<<tgrid, 64>>>(targets, T, W0, W1, W2);

    int nb0 = (3*HW0 + 255)/256;
    int nb1 = (3*HW1 + 255)/256;
    int nb2 = (3*HW2 + 255)/256;
    dim3 lgrid(nb0 + nb1 + nb2, B);
    k_loss<<<lgrid, 256>>>(r0, r1, r2, HW0, W0, HW1, W1, HW2, W2, nb0, nb0 + nb1);

    k_fin<<<1,1>>>((float*)d_out);
}